// round 1
// baseline (speedup 1.0000x reference)
#include <cuda_runtime.h>
#include <math.h>

#define BB 8
#define NN 16384
#define KK 128
#define CC 128
#define LL 4
#define NSPLIT 64
#define XPART (NN / NSPLIT)   // 256

// ---------------- scratch (global device arrays; no allocation) ----------------
__device__ float g_bases_c[BB * NN * KK];           // 64 MB
__device__ float g_bases_s[BB * NN * KK];           // 64 MB
__device__ float g_h[BB * CC * NN];                 // 64 MB
__device__ float g_h2[BB * CC * NN];                // 64 MB
__device__ float g_pc[NSPLIT * BB * CC * KK];       // 33.5 MB
__device__ float g_ps[NSPLIT * BB * CC * KK];       // 33.5 MB
__device__ float g_xc[BB * CC * KK];
__device__ float g_xs[BB * CC * KK];
__device__ float g_x0v[BB * CC];
__device__ float g_f0v[BB * CC];
__device__ float g_fc[BB * CC * KK];
__device__ float g_fs[BB * CC * KK];

__device__ __forceinline__ float gelu_exact(float v) {
    return 0.5f * v * (1.0f + erff(v * 0.70710678118654752f));
}

// ---------------- bases: cos/sin(nodes . modes) * mask ----------------
__global__ void bases_kernel(const float* __restrict__ nodes,
                             const float* __restrict__ mask,
                             const float* __restrict__ modes) {
    int gid = blockIdx.x * blockDim.x + threadIdx.x;   // over BB*NN*KK, k fastest
    int k = gid & (KK - 1);
    int bn = gid >> 7;                                  // b*NN + n
    float n0 = nodes[bn * 2 + 0], n1 = nodes[bn * 2 + 1];
    float m = mask[bn];
    float t = n0 * modes[k * 2 + 0] + n1 * modes[k * 2 + 1];
    float s, c;
    sincosf(t, &s, &c);
    g_bases_c[gid] = c * m;
    g_bases_s[gid] = s * m;
}

// ---------------- fc0: h[b][c][n] = x[b,n,:] @ fc0_w + b ----------------
__global__ void fc0_kernel(const float* __restrict__ x,
                           const float* __restrict__ w,
                           const float* __restrict__ bias) {
    int gid = blockIdx.x * blockDim.x + threadIdx.x;   // over BB*CC*NN, n fastest
    int n = gid & (NN - 1);
    int c = (gid >> 14) & (CC - 1);
    int b = gid >> 21;
    const float* xp = x + (b * NN + n) * 3;
    float v = bias[c] + xp[0] * w[c] + xp[1] * w[CC + c] + xp[2] * w[2 * CC + c];
    g_h[gid] = v;
}

// ---------------- forward projection (split-K GEMM) ----------------
// partial_c[split,b,i,k] = sum_{x in split} h[b,i,x] * bases_c[b,x,k] * nw[b,x]
__global__ __launch_bounds__(256, 1) void fwd_kernel(const float* __restrict__ h,
                                                     const float* __restrict__ nw) {
    __shared__ float Hst[32][128];   // [xx][i]
    __shared__ float Bc[32][128];    // [xx][k]
    __shared__ float Bss[32][128];   // [xx][k]
    int split = blockIdx.x, b = blockIdx.y;
    int tid = threadIdx.x;
    int tx = tid & 15, ty = tid >> 4;
    int i0 = ty * 8, k0 = tx * 8;
    const float* hb = h + (b * CC) * NN;
    const float* bcb = g_bases_c + (b * NN) * KK;
    const float* bsb = g_bases_s + (b * NN) * KK;
    const float* nwb = nw + b * NN;
    float aC[8][8], aS[8][8];
#pragma unroll
    for (int m = 0; m < 8; m++)
#pragma unroll
        for (int n = 0; n < 8; n++) { aC[m][n] = 0.f; aS[m][n] = 0.f; }

    int xbase = split * XPART;
    for (int xc = 0; xc < XPART; xc += 32) {
        int x0 = xbase + xc;
        // h tile: [128 i][32 x] -> transposed into Hst[xx][i]
#pragma unroll
        for (int j = 0; j < 4; j++) {
            int idx = tid + j * 256;
            int row = idx >> 3, c4 = (idx & 7) << 2;   // row=i, c4=x offset
            float4 v = *(const float4*)(hb + row * NN + x0 + c4);
            Hst[c4 + 0][row] = v.x;
            Hst[c4 + 1][row] = v.y;
            Hst[c4 + 2][row] = v.z;
            Hst[c4 + 3][row] = v.w;
        }
        // bases tiles: [32 x][128 k], weighted by nw
#pragma unroll
        for (int j = 0; j < 4; j++) {
            int idx = tid + j * 256;
            int row = idx >> 5, c4 = (idx & 31) << 2;  // row=x offset, c4=k offset
            float wgt = nwb[x0 + row];
            float4 v = *(const float4*)(bcb + (x0 + row) * KK + c4);
            v.x *= wgt; v.y *= wgt; v.z *= wgt; v.w *= wgt;
            *(float4*)&Bc[row][c4] = v;
            float4 u = *(const float4*)(bsb + (x0 + row) * KK + c4);
            u.x *= wgt; u.y *= wgt; u.z *= wgt; u.w *= wgt;
            *(float4*)&Bss[row][c4] = u;
        }
        __syncthreads();
#pragma unroll 4
        for (int xx = 0; xx < 32; xx++) {
            float4 a0 = *(float4*)&Hst[xx][i0];
            float4 a1 = *(float4*)&Hst[xx][i0 + 4];
            float4 c0 = *(float4*)&Bc[xx][k0];
            float4 c1 = *(float4*)&Bc[xx][k0 + 4];
            float4 s0 = *(float4*)&Bss[xx][k0];
            float4 s1 = *(float4*)&Bss[xx][k0 + 4];
            float av[8] = {a0.x, a0.y, a0.z, a0.w, a1.x, a1.y, a1.z, a1.w};
            float cv[8] = {c0.x, c0.y, c0.z, c0.w, c1.x, c1.y, c1.z, c1.w};
            float sv[8] = {s0.x, s0.y, s0.z, s0.w, s1.x, s1.y, s1.z, s1.w};
#pragma unroll
            for (int m = 0; m < 8; m++)
#pragma unroll
                for (int n = 0; n < 8; n++) {
                    aC[m][n] += av[m] * cv[n];
                    aS[m][n] += av[m] * sv[n];
                }
        }
        __syncthreads();
    }
    float* pc = g_pc + ((split * BB + b) * CC) * KK;
    float* ps = g_ps + ((split * BB + b) * CC) * KK;
#pragma unroll
    for (int m = 0; m < 8; m++) {
        int off = (i0 + m) * KK + k0;
        *(float4*)&pc[off] = make_float4(aC[m][0], aC[m][1], aC[m][2], aC[m][3]);
        *(float4*)&pc[off + 4] = make_float4(aC[m][4], aC[m][5], aC[m][6], aC[m][7]);
        *(float4*)&ps[off] = make_float4(aS[m][0], aS[m][1], aS[m][2], aS[m][3]);
        *(float4*)&ps[off + 4] = make_float4(aS[m][4], aS[m][5], aS[m][6], aS[m][7]);
    }
}

// ---------------- reduce partials -> x_c_hat, x_s_hat(-) ----------------
__global__ void reduce_kernel() {
    int gid = blockIdx.x * blockDim.x + threadIdx.x;   // BB*CC*KK
    float sc = 0.f, ss = 0.f;
#pragma unroll
    for (int s = 0; s < NSPLIT; s++) {
        sc += g_pc[s * BB * CC * KK + gid];
        ss += g_ps[s * BB * CC * KK + gid];
    }
    g_xc[gid] = sc;
    g_xs[gid] = -ss;   // reference: x_s_hat = -einsum(...)
}

// ---------------- x_0_hat[b,i] = sum_x h * nw * mask ----------------
__global__ void x0_kernel(const float* __restrict__ h,
                          const float* __restrict__ nw,
                          const float* __restrict__ mask) {
    int i = blockIdx.x, b = blockIdx.y;
    const float* hr = h + (b * CC + i) * NN;
    const float* nwb = nw + b * NN;
    const float* mb = mask + b * NN;
    float acc = 0.f;
    for (int x = threadIdx.x; x < NN; x += 256)
        acc += hr[x] * nwb[x] * mb[x];
    __shared__ float red[256];
    red[threadIdx.x] = acc;
    __syncthreads();
    for (int s = 128; s > 0; s >>= 1) {
        if (threadIdx.x < s) red[threadIdx.x] += red[threadIdx.x + s];
        __syncthreads();
    }
    if (threadIdx.x == 0) g_x0v[b * CC + i] = red[0];
}

// ---------------- f_0_hat[b,o] = sum_i x_0[b,i] * w0[l,i,o] ----------------
__global__ void f0_kernel(const float* __restrict__ w0, int l) {
    int b = blockIdx.x, o = threadIdx.x;
    __shared__ float xs[CC];
    xs[o] = g_x0v[b * CC + o];
    __syncthreads();
    const float* w = w0 + l * CC * CC;
    float acc = 0.f;
#pragma unroll 8
    for (int i = 0; i < CC; i++) acc += xs[i] * w[i * CC + o];
    g_f0v[b * CC + o] = acc;
}

// ---------------- complex weight mixing (k-contiguous, coalesced) ----------------
__global__ void mix_kernel(const float* __restrict__ wc,
                           const float* __restrict__ ws, int l) {
    int o = blockIdx.x, b = blockIdx.y, k = threadIdx.x;
    const float* wcl = wc + l * CC * CC * KK;
    const float* wsl = ws + l * CC * CC * KK;
    float fcA = 0.f, fsA = 0.f;
#pragma unroll 4
    for (int i = 0; i < CC; i++) {
        float xc = g_xc[(b * CC + i) * KK + k];
        float xsv = g_xs[(b * CC + i) * KK + k];
        float wcv = wcl[(i * CC + o) * KK + k];
        float wsv = wsl[(i * CC + o) * KK + k];
        fcA += xc * wcv - xsv * wsv;
        fsA += xsv * wcv + xc * wsv;
    }
    g_fc[(b * CC + o) * KK + k] = fcA;
    g_fs[(b * CC + o) * KK + k] = fsA;
}

// ---------------- inverse projection + conv + bias + f0*mask + gelu ----------------
// hout[b,o,x] = 2*fc@bases_c^T - 2*fs@bases_s^T + conv_w@h + conv_b + f0*mask, opt gelu
__global__ __launch_bounds__(256, 2) void inv_kernel(const float* __restrict__ hin,
                                                     float* __restrict__ hout,
                                                     const float* __restrict__ convw,
                                                     const float* __restrict__ convb,
                                                     const float* __restrict__ mask,
                                                     int l, int apply_gelu) {
    __shared__ float Ast[32][128];   // [cc][o]
    __shared__ float Bs[32][128];    // [cc][x]
    int x0 = blockIdx.x * 128, b = blockIdx.y;
    int tid = threadIdx.x;
    int tx = tid & 15, ty = tid >> 4;
    int o0 = ty * 8, xf0 = tx * 8;
    float acc[8][8];
#pragma unroll
    for (int m = 0; m < 8; m++)
#pragma unroll
        for (int n = 0; n < 8; n++) acc[m][n] = 0.f;

    for (int pass = 0; pass < 3; pass++) {
        const float* A;
        const float* Bsrc;
        float scale;
        if (pass == 0)      { A = g_fc + (b * CC) * KK; Bsrc = g_bases_c + (b * NN) * KK; scale = 2.f; }
        else if (pass == 1) { A = g_fs + (b * CC) * KK; Bsrc = g_bases_s + (b * NN) * KK; scale = -2.f; }
        else                { A = convw + l * CC * CC;  Bsrc = hin + (b * CC) * NN;       scale = 1.f; }

        for (int c0 = 0; c0 < 128; c0 += 32) {
            // A tile: source [o][contr] -> Ast[cc][o]
#pragma unroll
            for (int j = 0; j < 4; j++) {
                int idx = tid + j * 256;
                int row = idx >> 3, c4 = (idx & 7) << 2;   // row=o, c4=contr offset
                float4 v = *(const float4*)(A + row * 128 + c0 + c4);
                Ast[c4 + 0][row] = v.x * scale;
                Ast[c4 + 1][row] = v.y * scale;
                Ast[c4 + 2][row] = v.z * scale;
                Ast[c4 + 3][row] = v.w * scale;
            }
            if (pass < 2) {
                // bases [x][k]: transpose into Bs[kk][x]
#pragma unroll
                for (int j = 0; j < 4; j++) {
                    int idx = tid + j * 256;
                    int row = idx >> 3, c4 = (idx & 7) << 2;  // row=x offset, c4=k offset
                    float4 v = *(const float4*)(Bsrc + (x0 + row) * KK + c0 + c4);
                    Bs[c4 + 0][row] = v.x;
                    Bs[c4 + 1][row] = v.y;
                    Bs[c4 + 2][row] = v.z;
                    Bs[c4 + 3][row] = v.w;
                }
            } else {
                // h [i][x]: direct
#pragma unroll
                for (int j = 0; j < 4; j++) {
                    int idx = tid + j * 256;
                    int row = idx >> 5, c4 = (idx & 31) << 2;  // row=i offset, c4=x offset
                    *(float4*)&Bs[row][c4] = *(const float4*)(Bsrc + (c0 + row) * NN + x0 + c4);
                }
            }
            __syncthreads();
#pragma unroll 4
            for (int cc = 0; cc < 32; cc++) {
                float4 a0 = *(float4*)&Ast[cc][o0];
                float4 a1 = *(float4*)&Ast[cc][o0 + 4];
                float4 b0 = *(float4*)&Bs[cc][xf0];
                float4 b1 = *(float4*)&Bs[cc][xf0 + 4];
                float av[8] = {a0.x, a0.y, a0.z, a0.w, a1.x, a1.y, a1.z, a1.w};
                float bv[8] = {b0.x, b0.y, b0.z, b0.w, b1.x, b1.y, b1.z, b1.w};
#pragma unroll
                for (int m = 0; m < 8; m++)
#pragma unroll
                    for (int n = 0; n < 8; n++) acc[m][n] += av[m] * bv[n];
            }
            __syncthreads();
        }
    }
    // epilogue
    const float* mb = mask + b * NN + x0 + xf0;
#pragma unroll
    for (int m = 0; m < 8; m++) {
        int o = o0 + m;
        float f0v = g_f0v[b * CC + o];
        float cb = convb[l * CC + o];
        float* outp = hout + (b * CC + o) * NN + x0 + xf0;
#pragma unroll
        for (int n = 0; n < 8; n++) {
            float v = acc[m][n] + f0v * mb[n] + cb;
            if (apply_gelu) v = gelu_exact(v);
            outp[n] = v;
        }
    }
}

// ---------------- fc1: hout[b,j,x] = gelu(sum_c h[b,c,x]*fc1_w[c,j] + b1[j]) ----------------
__global__ __launch_bounds__(256, 2) void fc1_kernel(const float* __restrict__ hin,
                                                     float* __restrict__ hout,
                                                     const float* __restrict__ w1,
                                                     const float* __restrict__ b1) {
    __shared__ float Ast[32][128];   // [cc][j]  (fc1_w is [c][j]: direct copy)
    __shared__ float Bs[32][128];    // [cc][x]
    int x0 = blockIdx.x * 128, b = blockIdx.y;
    int tid = threadIdx.x;
    int tx = tid & 15, ty = tid >> 4;
    int o0 = ty * 8, xf0 = tx * 8;
    float acc[8][8];
#pragma unroll
    for (int m = 0; m < 8; m++)
#pragma unroll
        for (int n = 0; n < 8; n++) acc[m][n] = 0.f;

    for (int c0 = 0; c0 < 128; c0 += 32) {
#pragma unroll
        for (int j = 0; j < 4; j++) {
            int idx = tid + j * 256;
            int row = idx >> 5, c4 = (idx & 31) << 2;   // row=c offset, c4=j offset
            *(float4*)&Ast[row][c4] = *(const float4*)(w1 + (c0 + row) * 128 + c4);
        }
#pragma unroll
        for (int j = 0; j < 4; j++) {
            int idx = tid + j * 256;
            int row = idx >> 5, c4 = (idx & 31) << 2;
            *(float4*)&Bs[row][c4] = *(const float4*)(hin + (b * CC + c0 + row) * NN + x0 + c4);
        }
        __syncthreads();
#pragma unroll 4
        for (int cc = 0; cc < 32; cc++) {
            float4 a0 = *(float4*)&Ast[cc][o0];
            float4 a1 = *(float4*)&Ast[cc][o0 + 4];
            float4 b0 = *(float4*)&Bs[cc][xf0];
            float4 b1v = *(float4*)&Bs[cc][xf0 + 4];
            float av[8] = {a0.x, a0.y, a0.z, a0.w, a1.x, a1.y, a1.z, a1.w};
            float bv[8] = {b0.x, b0.y, b0.z, b0.w, b1v.x, b1v.y, b1v.z, b1v.w};
#pragma unroll
            for (int m = 0; m < 8; m++)
#pragma unroll
                for (int n = 0; n < 8; n++) acc[m][n] += av[m] * bv[n];
        }
        __syncthreads();
    }
#pragma unroll
    for (int m = 0; m < 8; m++) {
        int jj = o0 + m;
        float bj = b1[jj];
        float* outp = hout + (b * CC + jj) * NN + x0 + xf0;
#pragma unroll
        for (int n = 0; n < 8; n++) outp[n] = gelu_exact(acc[m][n] + bj);
    }
}

// ---------------- fc2 + mask ----------------
__global__ void fc2_kernel(const float* __restrict__ hin,
                           float* __restrict__ out,
                           const float* __restrict__ w2,
                           const float* __restrict__ b2,
                           const float* __restrict__ mask) {
    __shared__ float ws[128];
    int x0 = blockIdx.x * 128, b = blockIdx.y;
    ws[threadIdx.x] = w2[threadIdx.x];
    __syncthreads();
    int x = x0 + threadIdx.x;
    float acc = 0.f;
#pragma unroll 8
    for (int j = 0; j < 128; j++) acc += hin[(b * CC + j) * NN + x] * ws[j];
    out[b * NN + x] = (acc + b2[0]) * mask[b * NN + x];
}

// ---------------- launch ----------------
extern "C" void kernel_launch(void* const* d_in, const int* in_sizes, int n_in,
                              void* d_out, int out_size) {
    const float* x     = (const float*)d_in[0];
    const float* nodes = (const float*)d_in[1];
    const float* mask  = (const float*)d_in[2];
    const float* nw    = (const float*)d_in[3];
    const float* modes = (const float*)d_in[4];
    const float* fc0w  = (const float*)d_in[5];
    const float* fc0b  = (const float*)d_in[6];
    const float* wc    = (const float*)d_in[7];
    const float* ws_   = (const float*)d_in[8];
    const float* w0    = (const float*)d_in[9];
    const float* convw = (const float*)d_in[10];
    const float* convb = (const float*)d_in[11];
    const float* fc1w  = (const float*)d_in[12];
    const float* fc1b  = (const float*)d_in[13];
    const float* fc2w  = (const float*)d_in[14];
    const float* fc2b  = (const float*)d_in[15];
    float* out = (float*)d_out;

    float *hA = nullptr, *hB = nullptr;
    cudaGetSymbolAddress((void**)&hA, g_h);
    cudaGetSymbolAddress((void**)&hB, g_h2);

    bases_kernel<<<(BB * NN * KK) / 256, 256>>>(nodes, mask, modes);
    fc0_kernel<<<(BB * CC * NN) / 256, 256>>>(x, fc0w, fc0b);

    float* cur = hA;
    float* nxt = hB;
    for (int l = 0; l < LL; l++) {
        fwd_kernel<<<dim3(NSPLIT, BB), 256>>>(cur, nw);
        reduce_kernel<<<(BB * CC * KK) / 256, 256>>>();
        x0_kernel<<<dim3(CC, BB), 256>>>(cur, nw, mask);
        f0_kernel<<<BB, CC>>>(w0, l);
        mix_kernel<<<dim3(CC, BB), KK>>>(wc, ws_, l);
        inv_kernel<<<dim3(NN / 128, BB), 256>>>(cur, nxt, convw, convb, mask, l,
                                                (l != LL - 1) ? 1 : 0);
        float* t = cur; cur = nxt; nxt = t;
    }
    fc1_kernel<<<dim3(NN / 128, BB), 256>>>(cur, nxt, fc1w, fc1b);
    fc2_kernel<<<dim3(NN / 128, BB), 128>>>(nxt, out, fc2w, fc2b, mask);
}